// round 3
// baseline (speedup 1.0000x reference)
#include <cuda_runtime.h>
#include <cuda_bf16.h>

// Problem constants (fixed by the reference): B=256, T=2048, L=4, H=64, P=1.
#define BSZ   256
#define TLEN  2048
#define NLAY  4
#define HID   64
#define CHUNK 32          // timesteps per sync chunk (= warp width)
#define NCH   (TLEN/CHUNK)
#define RINGC 4           // ring capacity in chunks per layer boundary

__device__ __forceinline__ float sigm(float x) {
    return __fdividef(1.0f, 1.0f + __expf(-x));
}
__device__ __forceinline__ float tanh_f(float x) {
    x = fminf(fmaxf(x, -15.0f), 15.0f);   // guard __expf overflow -> NaN
    float e = __expf(-2.0f * x);
    return __fdividef(1.0f - e, 1.0f + e);
}
__device__ __forceinline__ float wsum(float v) {
    v += __shfl_xor_sync(0xffffffffu, v, 16);
    v += __shfl_xor_sync(0xffffffffu, v, 8);
    v += __shfl_xor_sync(0xffffffffu, v, 4);
    v += __shfl_xor_sync(0xffffffffu, v, 2);
    v += __shfl_xor_sync(0xffffffffu, v, 1);
    return v;
}

// One block per batch element; warp w == layer w (wavefront pipeline).
// Within a layer-warp: lane ln owns cells {ln, ln+32}; torch gate order i,f,g,o.
__global__ __launch_bounds__(128) void lstm_wave_kernel(
    const float* __restrict__ y,     // [B, T, 1]
    const float* __restrict__ Wih,   // [L, 256, 1]
    const float* __restrict__ Whh,   // [L, 256, 1]
    const float* __restrict__ bih,   // [L, 256]
    const float* __restrict__ bhh,   // [L, 256]
    const float* __restrict__ Whr,   // [L, 1, 64]
    const int*   __restrict__ mslp,
    float*       __restrict__ out)   // [B, T-msl, 1]
{
    __shared__ float ring_s[NLAY - 1][RINGC * CHUNK];
    __shared__ int   prog_s[NLAY];
    volatile int* prog = prog_s;

    const int b  = blockIdx.x;
    const int l  = threadIdx.x >> 5;   // layer == warp id
    const int ln = threadIdx.x & 31;

    if (threadIdx.x < NLAY) prog_s[threadIdx.x] = 0;
    __syncthreads();

    // ---- per-lane weights for this layer, register resident ----
    float wi[8], wh[8], bs[8];
    {
        const float* wih_l = Wih + l * 4 * HID;
        const float* whh_l = Whh + l * 4 * HID;
        const float* bih_l = bih + l * 4 * HID;
        const float* bhh_l = bhh + l * 4 * HID;
#pragma unroll
        for (int j = 0; j < 8; ++j) {
            int idx = (j >> 1) * 64 + ln + (j & 1) * 32;
            wi[j] = wih_l[idx];
            wh[j] = whh_l[idx];
            bs[j] = bih_l[idx] + bhh_l[idx];
        }
    }
    const float wr0 = Whr[l * HID + ln];
    const float wr1 = Whr[l * HID + ln + 32];

    const int   msl = *mslp;
    const int   To  = TLEN - msl;
    const float* yb = y + b * TLEN;

    float h = 0.0f, c0 = 0.0f, c1 = 0.0f;
    float xnext = (l == 0) ? yb[ln] : 0.0f;   // prefetch chunk 0 for layer 0

    for (int nc = 0; nc < NCH; ++nc) {
        const int tc = nc * CHUNK;

        // ---- obtain input chunk ----
        float xcur;
        if (l == 0) {
            xcur  = xnext;
            xnext = (nc + 1 < NCH) ? yb[tc + CHUNK + ln] : 0.0f;  // off-chain prefetch
        } else {
            while (prog[l - 1] < nc + 1) { }       // wait for producer chunk
            __threadfence_block();
            xcur = ring_s[l - 1][(nc & (RINGC - 1)) * CHUNK + ln];
        }

        // ---- producer back-pressure: consumer must have freed the ring slot ----
        if (l < NLAY - 1 && nc >= RINGC) {
            while (prog[l + 1] < nc - RINGC + 1) { }
        }

        // ---- 32 recurrence steps ----
        float keep = 0.0f;
#pragma unroll 8
        for (int tt = 0; tt < CHUNK; ++tt) {
            float x = __shfl_sync(0xffffffffu, xcur, tt);   // off the h-chain

            float g[8];
#pragma unroll
            for (int j = 0; j < 8; ++j)
                g[j] = fmaf(x, wi[j], fmaf(h, wh[j], bs[j]));

            float i0 = sigm(g[0]),   i1 = sigm(g[1]);
            float f0 = sigm(g[2]),   f1 = sigm(g[3]);
            float t0 = tanh_f(g[4]), t1 = tanh_f(g[5]);
            float o0 = sigm(g[6]),   o1 = sigm(g[7]);

            c0 = fmaf(f0, c0, i0 * t0);
            c1 = fmaf(f1, c1, i1 * t1);

            float part = fmaf(o0 * tanh_f(c0), wr0, o1 * tanh_f(c1) * wr1);
            h = wsum(part);                         // 64-wide dot finish

            keep = (tt == ln) ? h : keep;           // stage for coalesced emit
        }

        // ---- publish chunk ----
        if (l < NLAY - 1) {
            ring_s[l][(nc & (RINGC - 1)) * CHUNK + ln] = keep;
            __syncwarp();
            __threadfence_block();
            if (ln == 0) prog_s[l] = nc + 1;        // release to consumer
        } else {
            int t = tc + ln;
            if (t >= msl) out[b * To + (t - msl)] = keep;
            if (ln == 0) prog_s[l] = nc + 1;        // free producer's ring slot
        }
        if (l > 0 && l < NLAY - 1) { /* prog update above doubles as consume-ack */ }
        else if (l > 0 && l == NLAY - 1) { /* handled */ }
    }
}

extern "C" void kernel_launch(void* const* d_in, const int* in_sizes, int n_in,
                              void* d_out, int out_size) {
    const float* y    = (const float*)d_in[0];
    const float* Wih  = (const float*)d_in[1];
    const float* Whh  = (const float*)d_in[2];
    const float* bih  = (const float*)d_in[3];
    const float* bhh  = (const float*)d_in[4];
    const float* Whr  = (const float*)d_in[5];
    const int*   msl  = (const int*)  d_in[6];
    float* out = (float*)d_out;
    (void)in_sizes; (void)n_in; (void)out_size;

    lstm_wave_kernel<<<BSZ, 128>>>(y, Wih, Whh, bih, bhh, Whr, msl, out);
}

// round 4
// speedup vs baseline: 1.0771x; 1.0771x over previous
#include <cuda_runtime.h>
#include <cuda_bf16.h>

// Problem constants (fixed by the reference): B=256, T=2048, L=4, H=64, P=1.
#define BSZ   256
#define TLEN  2048
#define NLAY  4
#define HID   64
#define CHUNK 32          // timesteps per sync chunk (= warp width)
#define NCH   (TLEN/CHUNK)
#define RINGC 4           // ring capacity in chunks per layer boundary

__device__ __forceinline__ float sigm(float x) {
    return __fdividef(1.0f, 1.0f + __expf(-x));
}
__device__ __forceinline__ float tanh_f(float x) {
    x = fminf(fmaxf(x, -15.0f), 15.0f);   // guard __expf overflow -> NaN
    float e = __expf(-2.0f * x);
    return __fdividef(1.0f - e, 1.0f + e);
}
__device__ __forceinline__ float wsum(float v) {
    v += __shfl_xor_sync(0xffffffffu, v, 16);
    v += __shfl_xor_sync(0xffffffffu, v, 8);
    v += __shfl_xor_sync(0xffffffffu, v, 4);
    v += __shfl_xor_sync(0xffffffffu, v, 2);
    v += __shfl_xor_sync(0xffffffffu, v, 1);
    return v;
}

__device__ __forceinline__ unsigned sh_addr(const void* p) {
    return (unsigned)__cvta_generic_to_shared(p);
}
__device__ __forceinline__ int ld_vol_sh(unsigned a) {
    int v;
    asm volatile("ld.volatile.shared.u32 %0, [%1];" : "=r"(v) : "r"(a));
    return v;
}
__device__ __forceinline__ void st_vol_sh(unsigned a, int v) {
    asm volatile("st.volatile.shared.u32 [%0], %1;" :: "r"(a), "r"(v));
}
// Low-MIO-pressure wait: poll once, then poll with nanosleep backoff.
__device__ __forceinline__ void wait_ge(unsigned a, int need) {
    if (ld_vol_sh(a) >= need) return;
    while (ld_vol_sh(a) < need) __nanosleep(32);
}

// One block per batch element; warp w == layer w (wavefront pipeline over chunks).
// Lane ln owns cells {ln, ln+32}; torch gate order i, f, g, o.
__global__ __launch_bounds__(128) void lstm_wave_kernel(
    const float* __restrict__ y,     // [B, T, 1]
    const float* __restrict__ Wih,   // [L, 256, 1]
    const float* __restrict__ Whh,   // [L, 256, 1]
    const float* __restrict__ bih,   // [L, 256]
    const float* __restrict__ bhh,   // [L, 256]
    const float* __restrict__ Whr,   // [L, 1, 64]
    const int*   __restrict__ mslp,
    float*       __restrict__ out)   // [B, T-msl, 1]
{
    __shared__ float ring_s[NLAY - 1][RINGC * CHUNK];
    __shared__ int   prog_s[NLAY];

    const int b  = blockIdx.x;
    const int l  = threadIdx.x >> 5;   // layer == warp id (one per SMSP)
    const int ln = threadIdx.x & 31;

    if (threadIdx.x < NLAY) prog_s[threadIdx.x] = 0;
    __syncthreads();

    const unsigned my_prog   = sh_addr(&prog_s[l]);
    const unsigned up_prog   = (l > 0)        ? sh_addr(&prog_s[l - 1]) : 0u;
    const unsigned down_prog = (l < NLAY - 1) ? sh_addr(&prog_s[l + 1]) : 0u;

    // ---- per-lane weights for this layer, register resident ----
    float wi[8], wh[8], bs[8];
    {
        const float* wih_l = Wih + l * 4 * HID;
        const float* whh_l = Whh + l * 4 * HID;
        const float* bih_l = bih + l * 4 * HID;
        const float* bhh_l = bhh + l * 4 * HID;
#pragma unroll
        for (int j = 0; j < 8; ++j) {
            int idx = (j >> 1) * 64 + ln + (j & 1) * 32;
            wi[j] = wih_l[idx];
            wh[j] = whh_l[idx];
            bs[j] = bih_l[idx] + bhh_l[idx];
        }
    }
    const float wr0 = Whr[l * HID + ln];
    const float wr1 = Whr[l * HID + ln + 32];

    const int   msl = *mslp;
    const int   To  = TLEN - msl;
    const float* yb = y + b * TLEN;

    float h = 0.0f, c0 = 0.0f, c1 = 0.0f;
    float xnext = (l == 0) ? yb[ln] : 0.0f;   // prefetch chunk 0 for layer 0

    for (int nc = 0; nc < NCH; ++nc) {
        const int tc = nc * CHUNK;

        // ---- obtain input chunk ----
        float xcur;
        if (l == 0) {
            xcur  = xnext;
            xnext = (nc + 1 < NCH) ? yb[tc + CHUNK + ln] : 0.0f;  // off-chain prefetch
        } else {
            wait_ge(up_prog, nc + 1);          // producer published this chunk
            __threadfence_block();             // acquire: order ring read after flag
            xcur = ring_s[l - 1][(nc & (RINGC - 1)) * CHUNK + ln];
        }

        // ---- producer back-pressure: ring slot (nc & 3) must be consumed ----
        if (l < NLAY - 1 && nc >= RINGC)
            wait_ge(down_prog, nc - RINGC + 1);

        // ---- 32 recurrence steps ----
        float keep = 0.0f;
#pragma unroll 8
        for (int tt = 0; tt < CHUNK; ++tt) {
            float x = __shfl_sync(0xffffffffu, xcur, tt);   // off the h-chain

            // xb_j depends only on x -> computed off the h-critical-path
            float xb[8], g[8];
#pragma unroll
            for (int j = 0; j < 8; ++j) xb[j] = fmaf(x, wi[j], bs[j]);
#pragma unroll
            for (int j = 0; j < 8; ++j) g[j] = fmaf(h, wh[j], xb[j]);  // 1 FMA on chain

            float i0 = sigm(g[0]),   i1 = sigm(g[1]);
            float f0 = sigm(g[2]),   f1 = sigm(g[3]);
            float t0 = tanh_f(g[4]), t1 = tanh_f(g[5]);
            float o0 = sigm(g[6]),   o1 = sigm(g[7]);

            c0 = fmaf(f0, c0, i0 * t0);
            c1 = fmaf(f1, c1, i1 * t1);

            float part = fmaf(o0 * tanh_f(c0), wr0, o1 * tanh_f(c1) * wr1);
            h = wsum(part);                         // 64-wide dot finish (5 hops)

            keep = (tt == ln) ? h : keep;           // stage for coalesced emit
        }

        // ---- publish chunk: explicit volatile release store ----
        if (l < NLAY - 1) {
            ring_s[l][(nc & (RINGC - 1)) * CHUNK + ln] = keep;
            __syncwarp();
            __threadfence_block();                  // release: ring before flag
            if (ln == 0) st_vol_sh(my_prog, nc + 1);
        } else {
            int t = tc + ln;
            if (t >= msl) out[b * To + (t - msl)] = keep;
            if (ln == 0) st_vol_sh(my_prog, nc + 1);  // ack for layer L-2 back-pressure
        }
    }
}

extern "C" void kernel_launch(void* const* d_in, const int* in_sizes, int n_in,
                              void* d_out, int out_size) {
    const float* y    = (const float*)d_in[0];
    const float* Wih  = (const float*)d_in[1];
    const float* Whh  = (const float*)d_in[2];
    const float* bih  = (const float*)d_in[3];
    const float* bhh  = (const float*)d_in[4];
    const float* Whr  = (const float*)d_in[5];
    const int*   msl  = (const int*)  d_in[6];
    float* out = (float*)d_out;
    (void)in_sizes; (void)n_in; (void)out_size;

    lstm_wave_kernel<<<BSZ, 128>>>(y, Wih, Whh, bih, bhh, Whr, msl, out);
}

// round 9
// speedup vs baseline: 1.1488x; 1.0666x over previous
#include <cuda_runtime.h>
#include <cuda_bf16.h>

// Problem constants (fixed by the reference): B=256, T=2048, L=4, H=64, P=1.
#define BSZ   256
#define TLEN  2048
#define NLAY  4
#define HID   64
#define CHUNK 32          // timesteps per BSP iteration (= warp width)
#define NCH   (TLEN/CHUNK)

__device__ __forceinline__ float sigm(float x) {
    return __fdividef(1.0f, 1.0f + __expf(-x));
}
__device__ __forceinline__ float tanh_f(float x) {
    x = fminf(fmaxf(x, -15.0f), 15.0f);   // guard __expf overflow -> NaN
    float e = __expf(-2.0f * x);
    return __fdividef(1.0f - e, 1.0f + e);
}
__device__ __forceinline__ float wsum(float v) {
    v += __shfl_xor_sync(0xffffffffu, v, 16);
    v += __shfl_xor_sync(0xffffffffu, v, 8);
    v += __shfl_xor_sync(0xffffffffu, v, 4);
    v += __shfl_xor_sync(0xffffffffu, v, 2);
    v += __shfl_xor_sync(0xffffffffu, v, 1);
    return v;
}

// One block per batch element; warp w == layer w.
// BSP wavefront: at iteration it, warp l processes chunk nc = it - l.
// Double-buffered ring per layer boundary; ONE __syncthreads per iteration
// gives both RAW (producer@it-1 -> consumer@it) and WAR (consumer@it ->
// producer re-write @it+1) safety. No flags, no spins, no sleeps.
// Lane ln owns cells {ln, ln+32}; torch gate order i, f, g, o.
__global__ __launch_bounds__(128) void lstm_bsp_kernel(
    const float* __restrict__ y,     // [B, T, 1]
    const float* __restrict__ Wih,   // [L, 256, 1]
    const float* __restrict__ Whh,   // [L, 256, 1]
    const float* __restrict__ bih,   // [L, 256]
    const float* __restrict__ bhh,   // [L, 256]
    const float* __restrict__ Whr,   // [L, 1, 64]
    const int*   __restrict__ mslp,
    float*       __restrict__ out)   // [B, T-msl, 1]
{
    __shared__ float ring_s[NLAY - 1][2][CHUNK];

    const int b  = blockIdx.x;
    const int l  = threadIdx.x >> 5;   // layer == warp id (one per SMSP)
    const int ln = threadIdx.x & 31;

    // ---- per-lane weights for this layer, register resident ----
    float wi[8], wh[8], bs[8];
    {
        const float* wih_l = Wih + l * 4 * HID;
        const float* whh_l = Whh + l * 4 * HID;
        const float* bih_l = bih + l * 4 * HID;
        const float* bhh_l = bhh + l * 4 * HID;
#pragma unroll
        for (int j = 0; j < 8; ++j) {
            int idx = (j >> 1) * 64 + ln + (j & 1) * 32;
            wi[j] = wih_l[idx];
            wh[j] = whh_l[idx];
            bs[j] = bih_l[idx] + bhh_l[idx];
        }
    }
    const float wr0 = Whr[l * HID + ln];
    const float wr1 = Whr[l * HID + ln + 32];

    const int   msl = *mslp;
    const int   To  = TLEN - msl;
    const float* yb = y + b * TLEN;

    float h = 0.0f, c0 = 0.0f, c1 = 0.0f;
    float xpre = (l == 0) ? yb[ln] : 0.0f;   // prefetch chunk 0 for layer 0

    const int NIT = NCH + NLAY - 1;          // 67 wavefront iterations
    for (int it = 0; it < NIT; ++it) {
        const int nc  = it - l;
        const bool act = ((unsigned)nc < (unsigned)NCH);

        if (act) {
            // ---- obtain input chunk ----
            float xcur;
            if (l == 0) {
                xcur = xpre;
                xpre = (nc + 1 < NCH) ? yb[(nc + 1) * CHUNK + ln] : 0.0f; // off-chain prefetch
            } else {
                xcur = ring_s[l - 1][(it - 1) & 1][ln];  // produced at iteration it-1
            }

            // ---- 32 recurrence steps ----
            float keep = 0.0f;
#pragma unroll 8
            for (int tt = 0; tt < CHUNK; ++tt) {
                float x = __shfl_sync(0xffffffffu, xcur, tt);   // off the h-chain

                // xb_j depends only on x -> off the h-critical-path
                float xb[8], g[8];
#pragma unroll
                for (int j = 0; j < 8; ++j) xb[j] = fmaf(x, wi[j], bs[j]);
#pragma unroll
                for (int j = 0; j < 8; ++j) g[j] = fmaf(h, wh[j], xb[j]);  // 1 FMA on chain

                float i0 = sigm(g[0]),   i1 = sigm(g[1]);
                float f0 = sigm(g[2]),   f1 = sigm(g[3]);
                float t0 = tanh_f(g[4]), t1 = tanh_f(g[5]);
                float o0 = sigm(g[6]),   o1 = sigm(g[7]);

                c0 = fmaf(f0, c0, i0 * t0);
                c1 = fmaf(f1, c1, i1 * t1);

                float part = fmaf(o0 * tanh_f(c0), wr0, o1 * tanh_f(c1) * wr1);
                h = wsum(part);                         // 64-wide dot finish (5 hops)

                keep = (tt == ln) ? h : keep;           // stage for coalesced emit
            }

            // ---- publish chunk ----
            if (l < NLAY - 1) {
                ring_s[l][it & 1][ln] = keep;
            } else {
                int t = nc * CHUNK + ln;
                if (t >= msl) out[b * To + (t - msl)] = keep;
            }
        }

        __syncthreads();   // single barrier: RAW + WAR for the double buffer
    }
}

extern "C" void kernel_launch(void* const* d_in, const int* in_sizes, int n_in,
                              void* d_out, int out_size) {
    const float* y    = (const float*)d_in[0];
    const float* Wih  = (const float*)d_in[1];
    const float* Whh  = (const float*)d_in[2];
    const float* bih  = (const float*)d_in[3];
    const float* bhh  = (const float*)d_in[4];
    const float* Whr  = (const float*)d_in[5];
    const int*   msl  = (const int*)  d_in[6];
    float* out = (float*)d_out;
    (void)in_sizes; (void)n_in; (void)out_size;

    lstm_bsp_kernel<<<BSZ, 128>>>(y, Wih, Whh, bih, bhh, Whr, msl, out);
}

// round 10
// speedup vs baseline: 1.9403x; 1.6889x over previous
#include <cuda_runtime.h>
#include <cuda_bf16.h>

// Problem constants (fixed by the reference): B=256, T=2048, L=4, H=64, P=1.
#define BSZ   256
#define TLEN  2048
#define NLAY  4
#define HID   64
#define CHUNK 32          // timesteps per BSP iteration (= warp width)
#define NCH   (TLEN/CHUNK)

#define L2E 1.4426950408889634f   // log2(e)

__device__ __forceinline__ float ex2(float x) {
    float r; asm("ex2.approx.ftz.f32 %0, %1;" : "=f"(r) : "f"(x)); return r;
}
__device__ __forceinline__ float rcpa(float x) {
    float r; asm("rcp.approx.ftz.f32 %0, %1;" : "=f"(r) : "f"(x)); return r;
}
__device__ __forceinline__ float wsum(float v) {
    v += __shfl_xor_sync(0xffffffffu, v, 16);
    v += __shfl_xor_sync(0xffffffffu, v, 8);
    v += __shfl_xor_sync(0xffffffffu, v, 4);
    v += __shfl_xor_sync(0xffffffffu, v, 2);
    v += __shfl_xor_sync(0xffffffffu, v, 1);
    return v;
}

// One block per batch element; warp w == layer w (BSP wavefront over chunks).
// Lane ln owns cells {ln, ln+32}; torch gate order i, f, g, o.
// Weights are pre-scaled so the gate FMA directly yields the EX2 argument:
//   sigm gates (i,f,o): a = -L2E*g      -> sigm = 1/(1+2^a)
//   tanh gate  (g):     a = -2*L2E*g    -> tanh = (1-2^a)/(1+2^a)
// All 8 denominators share ONE rcp via a product tree (Montgomery batch);
// the two tanh(c) denominators share a second rcp. MUFU/step: 10 EX2 + 2 RCP.
__global__ __launch_bounds__(128) void lstm_bsp_kernel(
    const float* __restrict__ y,     // [B, T, 1]
    const float* __restrict__ Wih,   // [L, 256, 1]
    const float* __restrict__ Whh,   // [L, 256, 1]
    const float* __restrict__ bih,   // [L, 256]
    const float* __restrict__ bhh,   // [L, 256]
    const float* __restrict__ Whr,   // [L, 1, 64]
    const int*   __restrict__ mslp,
    float*       __restrict__ out)   // [B, T-msl, 1]
{
    __shared__ float ring_s[NLAY - 1][2][CHUNK];

    const int b  = blockIdx.x;
    const int l  = threadIdx.x >> 5;   // layer == warp id (one per SMSP)
    const int ln = threadIdx.x & 31;

    // ---- per-lane weights, pre-scaled, register resident ----
    float wi[8], wh[8], bs[8];
    {
        const float* wih_l = Wih + l * 4 * HID;
        const float* whh_l = Whh + l * 4 * HID;
        const float* bih_l = bih + l * 4 * HID;
        const float* bhh_l = bhh + l * 4 * HID;
#pragma unroll
        for (int j = 0; j < 8; ++j) {
            int gate = j >> 1;                      // 0:i 1:f 2:g 3:o
            int idx  = gate * 64 + ln + (j & 1) * 32;
            float s  = (gate == 2) ? (-2.0f * L2E) : (-L2E);
            wi[j] = s * wih_l[idx];
            wh[j] = s * whh_l[idx];
            bs[j] = s * (bih_l[idx] + bhh_l[idx]);
        }
    }
    const float wr0 = Whr[l * HID + ln];
    const float wr1 = Whr[l * HID + ln + 32];

    const int   msl = *mslp;
    const int   To  = TLEN - msl;
    const float* yb = y + b * TLEN;

    float h = 0.0f, c0 = 0.0f, c1 = 0.0f;
    float xpre = (l == 0) ? yb[ln] : 0.0f;   // prefetch chunk 0 for layer 0

    const int NIT = NCH + NLAY - 1;          // 67 wavefront iterations
    for (int it = 0; it < NIT; ++it) {
        const int nc  = it - l;
        const bool act = ((unsigned)nc < (unsigned)NCH);

        if (act) {
            // ---- obtain input chunk ----
            float xcur;
            if (l == 0) {
                xcur = xpre;
                xpre = (nc + 1 < NCH) ? yb[(nc + 1) * CHUNK + ln] : 0.0f; // off-chain prefetch
            } else {
                xcur = ring_s[l - 1][(it - 1) & 1][ln];  // produced at iteration it-1
            }

            // ---- 32 recurrence steps ----
            float keep = 0.0f;
#pragma unroll 8
            for (int tt = 0; tt < CHUNK; ++tt) {
                float x = __shfl_sync(0xffffffffu, xcur, tt);   // off the h-chain

                // xb depends only on x -> off the h-critical-path
                float xb[8], e[8], d[8];
#pragma unroll
                for (int j = 0; j < 8; ++j) xb[j] = fmaf(x, wi[j], bs[j]);
#pragma unroll
                for (int j = 0; j < 8; ++j) {
                    float a = fmaf(h, wh[j], xb[j]);            // 1 FMA on chain
                    a = fminf(a, 14.0f);   // keep 8-product < 2^128 (inf poisons batch)
                    e[j] = ex2(a);
                    d[j] = 1.0f + e[j];
                }

                // ---- Montgomery batched reciprocal of the 8 denominators ----
                float p01 = d[0] * d[1], p23 = d[2] * d[3];
                float p45 = d[4] * d[5], p67 = d[6] * d[7];
                float pA  = p01 * p23,   pB  = p45 * p67;
                float r   = rcpa(pA * pB);                      // ONE rcp for 8
                float rA  = r * pB,      rB2 = r * pA;
                float r01 = rA * p23,    r23 = rA * p01;
                float r45 = rB2 * p67,   r67 = rB2 * p45;
                float i0 = r01 * d[1],   i1 = r01 * d[0];       // sigm(i)
                float f0 = r23 * d[3],   f1 = r23 * d[2];       // sigm(f)
                float g0 = r45 * d[5],   g1 = r45 * d[4];       // 1/(1+e) for tanh(g)
                float o0 = r67 * d[7],   o1 = r67 * d[6];       // sigm(o)

                float tg0 = (1.0f - e[4]) * g0;                 // tanh(g)
                float tg1 = (1.0f - e[5]) * g1;

                c0 = fmaf(f0, c0, i0 * tg0);
                c1 = fmaf(f1, c1, i1 * tg1);

                // tanh(c): shared rcp for both denominators
                float ac0 = fminf(c0 * (-2.0f * L2E), 14.0f);
                float ac1 = fminf(c1 * (-2.0f * L2E), 14.0f);
                float ec0 = ex2(ac0), ec1 = ex2(ac1);
                float dc0 = 1.0f + ec0, dc1 = 1.0f + ec1;
                float rc  = rcpa(dc0 * dc1);                    // ONE rcp for 2
                float tc0 = (1.0f - ec0) * (rc * dc1);
                float tc1 = (1.0f - ec1) * (rc * dc0);

                float part = fmaf(o0 * tc0, wr0, (o1 * tc1) * wr1);
                h = wsum(part);                                 // 64-wide allreduce (5 bfly)

                keep = (tt == ln) ? h : keep;                   // stage for coalesced emit
            }

            // ---- publish chunk ----
            if (l < NLAY - 1) {
                ring_s[l][it & 1][ln] = keep;
            } else {
                int t = nc * CHUNK + ln;
                if (t >= msl) out[b * To + (t - msl)] = keep;
            }
        }

        __syncthreads();   // single barrier: RAW + WAR for the double buffer
    }
}

extern "C" void kernel_launch(void* const* d_in, const int* in_sizes, int n_in,
                              void* d_out, int out_size) {
    const float* y    = (const float*)d_in[0];
    const float* Wih  = (const float*)d_in[1];
    const float* Whh  = (const float*)d_in[2];
    const float* bih  = (const float*)d_in[3];
    const float* bhh  = (const float*)d_in[4];
    const float* Whr  = (const float*)d_in[5];
    const int*   msl  = (const int*)  d_in[6];
    float* out = (float*)d_out;
    (void)in_sizes; (void)n_in; (void)out_size;

    lstm_bsp_kernel<<<BSZ, 128>>>(y, Wih, Whh, bih, bhh, Whr, msl, out);
}